// round 1
// baseline (speedup 1.0000x reference)
#include <cuda_runtime.h>

// ============================================================================
// GraphCastProcessor: 6-layer message-passing GNN, L=256.
// Per layer:
//   h   = x[dst] @ We[:256] + x[src] @ We[256:512] + ea @ We[512:516] + be
//   msg = silu(LN(h, g1, b1))                 (edge kernel, fused, atomics -> agg)
//   u   = x @ Wn1[:256] + agg @ Wn1[256:] + b ; t = silu(LN(u, g2, b2))  (node1)
//   x   = x + t @ Wn2 + b2                    (node2)
// All fp32. Tile: 32 rows x 256 cols per block, 256 threads,
// per-thread 4 rows x 8 cols; warp w owns rows {w, w+8, w+16, w+24} so LN is a
// pure warp reduction.
// ============================================================================

#define MAXN 40962
#define MAXD 163848

__device__ float g_bufA[MAXN * 256];
__device__ float g_bufB[MAXN * 256];
__device__ float g_agg [MAXN * 256];
__device__ float g_tmp [MAXN * 256];

__device__ __forceinline__ float fast_silu(float y) {
    // y * sigmoid(y); __expf/__fdividef err ~1e-6 rel, fine for 1e-3 budget
    return __fdividef(y, 1.0f + __expf(-y));
}

// One K-chunk of the 32x256 GEMM tile.
// cols per thread: j<4 -> tx*4+j ; j>=4 -> 128+tx*4+(j-4)  (conflict-free LDS.128)
template <int KC>
__device__ __forceinline__ void gemm_chunk(const float (&sA)[32][16],
                                           const float (&sW)[16][256],
                                           int wy, int tx, float acc[4][8]) {
#pragma unroll
    for (int k = 0; k < KC; k++) {
        float a[4];
        a[0] = sA[wy][k];      a[1] = sA[wy + 8][k];
        a[2] = sA[wy + 16][k]; a[3] = sA[wy + 24][k];
        float w[8];
        *(float4*)&w[0] = *(const float4*)&sW[k][tx * 4];
        *(float4*)&w[4] = *(const float4*)&sW[k][128 + tx * 4];
#pragma unroll
        for (int i = 0; i < 4; i++)
#pragma unroll
            for (int j = 0; j < 8; j++)
                acc[i][j] = fmaf(a[i], w[j], acc[i][j]);
    }
}

// LayerNorm (256) + SiLU over one row held as 8 values/lane across a warp.
__device__ __forceinline__ void ln_silu_row(float v[8], int tx,
                                            const float* sG, const float* sB) {
    float s = v[0] + v[1] + v[2] + v[3] + v[4] + v[5] + v[6] + v[7];
#pragma unroll
    for (int o = 16; o > 0; o >>= 1) s += __shfl_xor_sync(0xffffffffu, s, o);
    float mean = s * (1.0f / 256.0f);
    float vs = 0.f;
#pragma unroll
    for (int j = 0; j < 8; j++) { float d = v[j] - mean; vs += d * d; }
#pragma unroll
    for (int o = 16; o > 0; o >>= 1) vs += __shfl_xor_sync(0xffffffffu, vs, o);
    float rstd = rsqrtf(vs * (1.0f / 256.0f) + 1e-5f);
#pragma unroll
    for (int j = 0; j < 8; j++) {
        int col = (j < 4) ? (tx * 4 + j) : (128 + tx * 4 + j - 4);
        float y = (v[j] - mean) * rstd * sG[col] + sB[col];
        v[j] = fast_silu(y);
    }
}

// ---------------------------------------------------------------------------
// Edge kernel: per 32-edge tile compute h, LN, silu, atomic scatter-add to agg
// ---------------------------------------------------------------------------
__global__ __launch_bounds__(256) void edge_kernel(
    const float* __restrict__ x, const int* __restrict__ eidx,  // [2*D]: src, dst
    const float* __restrict__ ea,                               // [D,4]
    const float* __restrict__ Ww,                               // [516,256] (layer slice)
    const float* __restrict__ Wb, const float* __restrict__ gam,
    const float* __restrict__ bet, float* __restrict__ agg, int D) {
    __shared__ __align__(16) float sA[32][16];
    __shared__ __align__(16) float sW[16][256];
    __shared__ int sIdx[2][32];  // [0]=src, [1]=dst
    __shared__ float sBias[256], sG[256], sB[256];

    const int tid = threadIdx.x;
    const int tx = tid & 31, wy = tid >> 5;
    const int e0 = blockIdx.x * 32;

    if (tid < 64) {
        int p = tid >> 5, r = tid & 31;
        int e = e0 + r; if (e >= D) e = D - 1;
        sIdx[p][r] = eidx[(size_t)p * D + e];
    }
    sBias[tid] = Wb[tid];
    sG[tid] = gam[tid];
    sB[tid] = bet[tid];

    float acc[4][8];
#pragma unroll
    for (int i = 0; i < 4; i++)
#pragma unroll
        for (int j = 0; j < 8; j++) acc[i][j] = 0.f;

#pragma unroll 1
    for (int p = 0; p < 2; p++) {           // p=0: x[dst] rows 0..255, p=1: x[src] rows 256..511
        const float* Wp = Ww + (size_t)p * 256 * 256;
#pragma unroll 1
        for (int k0 = 0; k0 < 256; k0 += 16) {
            __syncthreads();
            if (tid < 128) {
                int r = tid >> 2, c = (tid & 3) * 4;
                int node = sIdx[1 - p][r];
                *(float4*)&sA[r][c] =
                    *(const float4*)(x + (size_t)node * 256 + k0 + c);
            }
            {
                int c4 = (tid & 63) * 4;
                int rb = (tid >> 6) * 4;
#pragma unroll
                for (int i = 0; i < 4; i++)
                    *(float4*)&sW[rb + i][c4] =
                        *(const float4*)(Wp + (size_t)(k0 + rb + i) * 256 + c4);
            }
            __syncthreads();
            gemm_chunk<16>(sA, sW, wy, tx, acc);
        }
    }

    // edge-attr phase: K=4, W rows 512..515
    __syncthreads();
    if (tid < 32) {
        int e = e0 + tid; if (e >= D) e = D - 1;
        *(float4*)&sA[tid][0] = *(const float4*)(ea + (size_t)e * 4);
    }
    {
        int c4 = (tid & 63) * 4;
        int kr = tid >> 6;
        *(float4*)&sW[kr][c4] =
            *(const float4*)(Ww + (size_t)(512 + kr) * 256 + c4);
    }
    __syncthreads();
    gemm_chunk<4>(sA, sW, wy, tx, acc);

#pragma unroll
    for (int i = 0; i < 4; i++) {
        int r = wy + 8 * i;
#pragma unroll
        for (int j = 0; j < 8; j++) {
            int col = (j < 4) ? (tx * 4 + j) : (128 + tx * 4 + j - 4);
            acc[i][j] += sBias[col];
        }
        ln_silu_row(acc[i], tx, sG, sB);
        int e = e0 + r;
        if (e < D) {
            float* ag = agg + (size_t)sIdx[1][r] * 256;
#pragma unroll
            for (int j = 0; j < 8; j++) {
                int col = (j < 4) ? (tx * 4 + j) : (128 + tx * 4 + j - 4);
                atomicAdd(ag + col, acc[i][j]);
            }
        }
    }
}

// ---------------------------------------------------------------------------
// Node kernel 1: t = silu(LN(x @ Wn1[:256] + agg @ Wn1[256:] + b))
// ---------------------------------------------------------------------------
__global__ __launch_bounds__(256) void node1_kernel(
    const float* __restrict__ x, const float* __restrict__ aggv,
    const float* __restrict__ Ww, const float* __restrict__ Wb,
    const float* __restrict__ gam, const float* __restrict__ bet,
    float* __restrict__ tout, int N) {
    __shared__ __align__(16) float sA[32][16];
    __shared__ __align__(16) float sW[16][256];
    __shared__ float sBias[256], sG[256], sB[256];

    const int tid = threadIdx.x;
    const int tx = tid & 31, wy = tid >> 5;
    const int n0 = blockIdx.x * 32;

    sBias[tid] = Wb[tid];
    sG[tid] = gam[tid];
    sB[tid] = bet[tid];

    float acc[4][8];
#pragma unroll
    for (int i = 0; i < 4; i++)
#pragma unroll
        for (int j = 0; j < 8; j++) acc[i][j] = 0.f;

#pragma unroll 1
    for (int p = 0; p < 2; p++) {
        const float* Ap = p ? aggv : x;
        const float* Wp = Ww + (size_t)p * 256 * 256;
#pragma unroll 1
        for (int k0 = 0; k0 < 256; k0 += 16) {
            __syncthreads();
            if (tid < 128) {
                int r = tid >> 2, c = (tid & 3) * 4;
                int row = n0 + r; if (row >= N) row = N - 1;
                *(float4*)&sA[r][c] =
                    *(const float4*)(Ap + (size_t)row * 256 + k0 + c);
            }
            {
                int c4 = (tid & 63) * 4;
                int rb = (tid >> 6) * 4;
#pragma unroll
                for (int i = 0; i < 4; i++)
                    *(float4*)&sW[rb + i][c4] =
                        *(const float4*)(Wp + (size_t)(k0 + rb + i) * 256 + c4);
            }
            __syncthreads();
            gemm_chunk<16>(sA, sW, wy, tx, acc);
        }
    }

#pragma unroll
    for (int i = 0; i < 4; i++) {
        int r = wy + 8 * i;
#pragma unroll
        for (int j = 0; j < 8; j++) {
            int col = (j < 4) ? (tx * 4 + j) : (128 + tx * 4 + j - 4);
            acc[i][j] += sBias[col];
        }
        ln_silu_row(acc[i], tx, sG, sB);
        if (n0 + r < N) {
            float4 lo = make_float4(acc[i][0], acc[i][1], acc[i][2], acc[i][3]);
            float4 hi = make_float4(acc[i][4], acc[i][5], acc[i][6], acc[i][7]);
            float* op = tout + (size_t)(n0 + r) * 256;
            *(float4*)(op + tx * 4) = lo;
            *(float4*)(op + 128 + tx * 4) = hi;
        }
    }
}

// ---------------------------------------------------------------------------
// Node kernel 2: out = x + t @ Wn2 + b2
// ---------------------------------------------------------------------------
__global__ __launch_bounds__(256) void node2_kernel(
    const float* __restrict__ tin, const float* __restrict__ xres,
    const float* __restrict__ Ww, const float* __restrict__ Wb,
    float* __restrict__ out, int N) {
    __shared__ __align__(16) float sA[32][16];
    __shared__ __align__(16) float sW[16][256];
    __shared__ float sBias[256];

    const int tid = threadIdx.x;
    const int tx = tid & 31, wy = tid >> 5;
    const int n0 = blockIdx.x * 32;

    sBias[tid] = Wb[tid];

    float acc[4][8];
#pragma unroll
    for (int i = 0; i < 4; i++)
#pragma unroll
        for (int j = 0; j < 8; j++) acc[i][j] = 0.f;

#pragma unroll 1
    for (int k0 = 0; k0 < 256; k0 += 16) {
        __syncthreads();
        if (tid < 128) {
            int r = tid >> 2, c = (tid & 3) * 4;
            int row = n0 + r; if (row >= N) row = N - 1;
            *(float4*)&sA[r][c] =
                *(const float4*)(tin + (size_t)row * 256 + k0 + c);
        }
        {
            int c4 = (tid & 63) * 4;
            int rb = (tid >> 6) * 4;
#pragma unroll
            for (int i = 0; i < 4; i++)
                *(float4*)&sW[rb + i][c4] =
                    *(const float4*)(Ww + (size_t)(k0 + rb + i) * 256 + c4);
        }
        __syncthreads();
        gemm_chunk<16>(sA, sW, wy, tx, acc);
    }

#pragma unroll
    for (int i = 0; i < 4; i++) {
        int r = wy + 8 * i;
        if (n0 + r < N) {
            const float* xr = xres + (size_t)(n0 + r) * 256;
            float4 xlo = *(const float4*)(xr + tx * 4);
            float4 xhi = *(const float4*)(xr + 128 + tx * 4);
            float4 lo, hi;
            lo.x = acc[i][0] + sBias[tx * 4 + 0] + xlo.x;
            lo.y = acc[i][1] + sBias[tx * 4 + 1] + xlo.y;
            lo.z = acc[i][2] + sBias[tx * 4 + 2] + xlo.z;
            lo.w = acc[i][3] + sBias[tx * 4 + 3] + xlo.w;
            hi.x = acc[i][4] + sBias[128 + tx * 4 + 0] + xhi.x;
            hi.y = acc[i][5] + sBias[128 + tx * 4 + 1] + xhi.y;
            hi.z = acc[i][6] + sBias[128 + tx * 4 + 2] + xhi.z;
            hi.w = acc[i][7] + sBias[128 + tx * 4 + 3] + xhi.w;
            float* op = out + (size_t)(n0 + r) * 256;
            *(float4*)(op + tx * 4) = lo;
            *(float4*)(op + 128 + tx * 4) = hi;
        }
    }
}

__global__ void zero_kernel(float4* __restrict__ p, int n4) {
    int i = blockIdx.x * blockDim.x + threadIdx.x;
    if (i < n4) p[i] = make_float4(0.f, 0.f, 0.f, 0.f);
}

// ---------------------------------------------------------------------------
extern "C" void kernel_launch(void* const* d_in, const int* in_sizes, int n_in,
                              void* d_out, int out_size) {
    const float* x_in  = (const float*)d_in[0];
    const int*   eidx  = (const int*)d_in[1];
    const float* ea    = (const float*)d_in[2];
    const float* We_w  = (const float*)d_in[3];
    const float* We_b  = (const float*)d_in[4];
    const float* g1    = (const float*)d_in[5];
    const float* b1    = (const float*)d_in[6];
    const float* Wn1_w = (const float*)d_in[7];
    const float* Wn1_b = (const float*)d_in[8];
    const float* g2    = (const float*)d_in[9];
    const float* b2    = (const float*)d_in[10];
    const float* Wn2_w = (const float*)d_in[11];
    const float* Wn2_b = (const float*)d_in[12];

    const int N  = in_sizes[0] / 256;
    const int D  = in_sizes[1] / 2;
    const int NL = in_sizes[4] / 256;

    float *bufA, *bufB, *aggp, *tmpp;
    cudaGetSymbolAddress((void**)&bufA, g_bufA);
    cudaGetSymbolAddress((void**)&bufB, g_bufB);
    cudaGetSymbolAddress((void**)&aggp, g_agg);
    cudaGetSymbolAddress((void**)&tmpp, g_tmp);

    const int nblk_e = (D + 31) / 32;
    const int nblk_n = (N + 31) / 32;
    const int n4 = (N * 256) / 4;
    const int zblk = (n4 + 255) / 256;

    const float* xcur = x_in;
    for (int l = 0; l < NL; l++) {
        float* xnext = (l == NL - 1) ? (float*)d_out
                                     : ((l & 1) ? bufB : bufA);
        zero_kernel<<<zblk, 256>>>((float4*)aggp, n4);
        edge_kernel<<<nblk_e, 256>>>(xcur, eidx, ea,
                                     We_w + (size_t)l * 516 * 256,
                                     We_b + (size_t)l * 256,
                                     g1 + (size_t)l * 256, b1 + (size_t)l * 256,
                                     aggp, D);
        node1_kernel<<<nblk_n, 256>>>(xcur, aggp,
                                      Wn1_w + (size_t)l * 512 * 256,
                                      Wn1_b + (size_t)l * 256,
                                      g2 + (size_t)l * 256, b2 + (size_t)l * 256,
                                      tmpp, N);
        node2_kernel<<<nblk_n, 256>>>(tmpp, xcur,
                                      Wn2_w + (size_t)l * 256 * 256,
                                      Wn2_b + (size_t)l * 256,
                                      xnext, N);
        xcur = xnext;
    }
}

// round 2
// speedup vs baseline: 1.6888x; 1.6888x over previous
#include <cuda_runtime.h>
#include <cuda_bf16.h>
#include <cstdint>

// ============================================================================
// GraphCastProcessor — split-bf16 tensor-core version.
// Per layer:
//   h   = x[dst]@We[:256] + x[src]@We[256:512] + ea@We[512:516] + be
//   msg = silu(LN(h,g1,b1)); agg = segsum(msg, dst)          (edge kernel)
//   u   = x@Wn1[:256] + agg@Wn1[256:] + b ; t = silu(LN(u))  (node1)
//   x   = x + t@Wn2 + b2                                     (node2)
// GEMMs via mma.sync.m16n8k16.bf16 with 2-way bf16 split (3 MMAs: hh+hl+lh),
// error ~2^-18 per product => near-fp32. Weights pre-split+packed per launch.
// Block tile 64 rows x 256 cols, 8 warps (2x4), K chunked by 16.
// ============================================================================

#define MAXN 40962
#define MAXD 163848
#define MAXNL 6

__device__ float g_bufA[MAXN * 256];
__device__ float g_bufB[MAXN * 256];
__device__ float g_agg [MAXN * 256];
__device__ float g_tmp [MAXN * 256];
// packed split weights: layout [layer][kpair][n] as uint2 {hi_pair, lo_pair}
__device__ uint2 g_We [MAXNL * 264 * 256];  // K padded 516 -> 528
__device__ uint2 g_Wn1[MAXNL * 256 * 256];  // K = 512
__device__ uint2 g_Wn2[MAXNL * 128 * 256];  // K = 256

// ---- dynamic smem layout (bytes) ----
#define SA_OFF    0                      // uint2 sA[64][9]   = 4608
#define SB_OFF    4608                   // uint2 sB[256][9]  = 18432
#define SOUT_OFF  23040                  // float sOut[64][260] = 66560
#define SIDX_OFF  89600                  // int   sIdx[2*64]  = 512
#define SBIAS_OFF (89600 + 512)          // float [256]
#define SG_OFF    (SBIAS_OFF + 1024)
#define SBV_OFF   (SG_OFF + 1024)
#define SMEM_BYTES (SBV_OFF + 1024)      // 93184

__device__ __forceinline__ float fast_silu(float y) {
    return __fdividef(y, 1.0f + __expf(-y));
}

// split a,b into (hi-pair, lo-pair) packed bf16x2
__device__ __forceinline__ uint2 split_pack(float a, float b) {
    __nv_bfloat16 h0 = __float2bfloat16(a);
    __nv_bfloat16 h1 = __float2bfloat16(b);
    __nv_bfloat16 l0 = __float2bfloat16(a - __bfloat162float(h0));
    __nv_bfloat16 l1 = __float2bfloat16(b - __bfloat162float(h1));
    uint2 r;
    r.x = (uint32_t)__bfloat16_as_ushort(h0) | ((uint32_t)__bfloat16_as_ushort(h1) << 16);
    r.y = (uint32_t)__bfloat16_as_ushort(l0) | ((uint32_t)__bfloat16_as_ushort(l1) << 16);
    return r;
}

__device__ __forceinline__ void mma_bf16(float c[4], const uint32_t a[4],
                                         uint32_t b0, uint32_t b1) {
    asm volatile(
        "mma.sync.aligned.m16n8k16.row.col.f32.bf16.bf16.f32 "
        "{%0,%1,%2,%3}, {%4,%5,%6,%7}, {%8,%9}, {%0,%1,%2,%3};"
        : "+f"(c[0]), "+f"(c[1]), "+f"(c[2]), "+f"(c[3])
        : "r"(a[0]), "r"(a[1]), "r"(a[2]), "r"(a[3]), "r"(b0), "r"(b1));
}

// LayerNorm(256) + SiLU over one row held as 8 vals/lane across a warp.
__device__ __forceinline__ void ln_silu_row(float v[8], int tx,
                                            const float* sG, const float* sB) {
    float s = v[0] + v[1] + v[2] + v[3] + v[4] + v[5] + v[6] + v[7];
#pragma unroll
    for (int o = 16; o > 0; o >>= 1) s += __shfl_xor_sync(0xffffffffu, s, o);
    float mean = s * (1.0f / 256.0f);
    float vs = 0.f;
#pragma unroll
    for (int j = 0; j < 8; j++) { float d = v[j] - mean; vs += d * d; }
#pragma unroll
    for (int o = 16; o > 0; o >>= 1) vs += __shfl_xor_sync(0xffffffffu, vs, o);
    float rstd = rsqrtf(vs * (1.0f / 256.0f) + 1e-5f);
#pragma unroll
    for (int j = 0; j < 8; j++) {
        int col = (j < 4) ? (tx * 4 + j) : (128 + tx * 4 + j - 4);
        float y = (v[j] - mean) * rstd * sG[col] + sB[col];
        v[j] = fast_silu(y);
    }
}

// weight packer: W [NL][Ksrc][256] fp32 -> out [NL][Kpad/2][256] uint2 split
__global__ void pack_weights(const float* __restrict__ W, uint2* __restrict__ out,
                             int Ksrc, int Kpad, int NL) {
    int idx = blockIdx.x * blockDim.x + threadIdx.x;
    int kp2 = Kpad >> 1;
    int total = NL * kp2 * 256;
    if (idx >= total) return;
    int n  = idx & 255;
    int kp = (idx >> 8) % kp2;
    int l  = idx / (256 * kp2);
    const float* Wl = W + (size_t)l * Ksrc * 256;
    int k0 = kp * 2;
    float a = (k0 < Ksrc)     ? Wl[(size_t)k0 * 256 + n]       : 0.f;
    float b = (k0 + 1 < Ksrc) ? Wl[(size_t)(k0 + 1) * 256 + n] : 0.f;
    out[idx] = split_pack(a, b);
}

__global__ void zero_kernel(float4* __restrict__ p, int n4) {
    int i = blockIdx.x * blockDim.x + threadIdx.x;
    if (i < n4) p[i] = make_float4(0.f, 0.f, 0.f, 0.f);
}

// ---- shared compute core pieces (expanded inline in each kernel) ----
// frag loads + 48 HMMA per warp per K16 chunk

// ---------------------------------------------------------------------------
// Edge kernel: tile of 64 edges; K = 528 (x[dst]:256, x[src]:256, ea:4+pad)
// ---------------------------------------------------------------------------
__global__ __launch_bounds__(256, 2) void edge_kernel(
    const float* __restrict__ x, const int* __restrict__ eidx,
    const float* __restrict__ ea, const uint2* __restrict__ Wp,
    const float* __restrict__ Wb, const float* __restrict__ gam,
    const float* __restrict__ bet, float* __restrict__ agg, int D) {
    extern __shared__ char smraw[];
    uint2 (*sA)[9]     = (uint2(*)[9])(smraw + SA_OFF);
    uint2 (*sB)[9]     = (uint2(*)[9])(smraw + SB_OFF);
    float (*sOut)[260] = (float(*)[260])(smraw + SOUT_OFF);
    int*   sIdx  = (int*)(smraw + SIDX_OFF);
    float* sBias = (float*)(smraw + SBIAS_OFF);
    float* sG    = (float*)(smraw + SG_OFF);
    float* sBv   = (float*)(smraw + SBV_OFF);

    const int tid = threadIdx.x;
    const int lane = tid & 31, warp = tid >> 5;
    const int wm = warp >> 2, wn = warp & 3;
    const int e0 = blockIdx.x * 64;
    const int arow = tid >> 2, ac4 = (tid & 3) * 4;

    if (tid < 128) {
        int p = tid >> 6, r = tid & 63;
        int e = e0 + r; if (e >= D) e = D - 1;
        sIdx[p * 64 + r] = eidx[(size_t)p * D + e];
    }
    sBias[tid] = Wb[tid]; sG[tid] = gam[tid]; sBv[tid] = bet[tid];

    float acc[2][8][4];
#pragma unroll
    for (int mt = 0; mt < 2; mt++)
#pragma unroll
        for (int nt = 0; nt < 8; nt++)
#pragma unroll
            for (int j = 0; j < 4; j++) acc[mt][nt][j] = 0.f;

#pragma unroll 1
    for (int chunk = 0; chunk < 33; chunk++) {
        __syncthreads();
        // --- stage A (64x16 fp32 -> split pairs) ---
        float4 v;
        if (chunk < 32) {
            int p = chunk >> 4;                 // 0: x[dst], 1: x[src]
            int kk = (chunk & 15) * 16;
            int node = sIdx[(1 - p) * 64 + arow];
            v = *(const float4*)(x + (size_t)node * 256 + kk + ac4);
        } else {
            v = make_float4(0.f, 0.f, 0.f, 0.f);
            if (ac4 == 0) {
                int e = e0 + arow; if (e >= D) e = D - 1;
                v = *(const float4*)(ea + (size_t)e * 4);
            }
        }
        sA[arow][(ac4 >> 1) + 0] = split_pack(v.x, v.y);
        sA[arow][(ac4 >> 1) + 1] = split_pack(v.z, v.w);
        // --- stage B (8 kpairs x 256 n) ---
        const uint2* Wc = Wp + (size_t)chunk * 8 * 256;
#pragma unroll
        for (int i = 0; i < 8; i++) sB[tid][i] = Wc[i * 256 + tid];
        __syncthreads();
        // --- compute ---
        uint32_t ah[2][4], al[2][4];
#pragma unroll
        for (int mt = 0; mt < 2; mt++) {
            int r = wm * 32 + mt * 16 + (lane >> 2);
            int q = lane & 3;
            uint2 v0 = sA[r][q], v1 = sA[r + 8][q];
            uint2 v2 = sA[r][q + 4], v3 = sA[r + 8][q + 4];
            ah[mt][0] = v0.x; ah[mt][1] = v1.x; ah[mt][2] = v2.x; ah[mt][3] = v3.x;
            al[mt][0] = v0.y; al[mt][1] = v1.y; al[mt][2] = v2.y; al[mt][3] = v3.y;
        }
#pragma unroll
        for (int nt = 0; nt < 8; nt++) {
            int n = wn * 64 + nt * 8 + (lane >> 2);
            uint2 b0 = sB[n][lane & 3];
            uint2 b1 = sB[n][(lane & 3) + 4];
#pragma unroll
            for (int mt = 0; mt < 2; mt++) {
                mma_bf16(acc[mt][nt], ah[mt], b0.x, b1.x);
                mma_bf16(acc[mt][nt], ah[mt], b0.y, b1.y);
                mma_bf16(acc[mt][nt], al[mt], b0.x, b1.x);
            }
        }
    }
    // --- epilogue: regs -> sOut (+bias) ---
#pragma unroll
    for (int mt = 0; mt < 2; mt++)
#pragma unroll
        for (int nt = 0; nt < 8; nt++) {
            int r0 = wm * 32 + mt * 16 + (lane >> 2);
            int c = wn * 64 + nt * 8 + 2 * (lane & 3);
            sOut[r0][c]     = acc[mt][nt][0] + sBias[c];
            sOut[r0][c + 1] = acc[mt][nt][1] + sBias[c + 1];
            sOut[r0 + 8][c]     = acc[mt][nt][2] + sBias[c];
            sOut[r0 + 8][c + 1] = acc[mt][nt][3] + sBias[c + 1];
        }
    __syncthreads();
    // --- LN + SiLU + atomic scatter-add ---
#pragma unroll 1
    for (int i = 0; i < 8; i++) {
        int r = i * 8 + warp;
        float vv[8];
        *(float4*)&vv[0] = *(float4*)&sOut[r][lane * 4];
        *(float4*)&vv[4] = *(float4*)&sOut[r][128 + lane * 4];
        ln_silu_row(vv, lane, sG, sBv);
        int e = e0 + r;
        if (e < D) {
            float* ag = agg + (size_t)sIdx[64 + r] * 256;
#pragma unroll
            for (int j = 0; j < 8; j++) {
                int col = (j < 4) ? (lane * 4 + j) : (128 + lane * 4 + j - 4);
                atomicAdd(ag + col, vv[j]);
            }
        }
    }
}

// ---------------------------------------------------------------------------
// Node kernel 1: t = silu(LN(x@Wn1[:256] + agg@Wn1[256:] + b)), K = 512
// ---------------------------------------------------------------------------
__global__ __launch_bounds__(256, 2) void node1_kernel(
    const float* __restrict__ x, const float* __restrict__ aggv,
    const uint2* __restrict__ Wp, const float* __restrict__ Wb,
    const float* __restrict__ gam, const float* __restrict__ bet,
    float* __restrict__ tout, int N) {
    extern __shared__ char smraw[];
    uint2 (*sA)[9]     = (uint2(*)[9])(smraw + SA_OFF);
    uint2 (*sB)[9]     = (uint2(*)[9])(smraw + SB_OFF);
    float (*sOut)[260] = (float(*)[260])(smraw + SOUT_OFF);
    float* sBias = (float*)(smraw + SBIAS_OFF);
    float* sG    = (float*)(smraw + SG_OFF);
    float* sBv   = (float*)(smraw + SBV_OFF);

    const int tid = threadIdx.x;
    const int lane = tid & 31, warp = tid >> 5;
    const int wm = warp >> 2, wn = warp & 3;
    const int n0 = blockIdx.x * 64;
    const int arow = tid >> 2, ac4 = (tid & 3) * 4;

    sBias[tid] = Wb[tid]; sG[tid] = gam[tid]; sBv[tid] = bet[tid];

    float acc[2][8][4];
#pragma unroll
    for (int mt = 0; mt < 2; mt++)
#pragma unroll
        for (int nt = 0; nt < 8; nt++)
#pragma unroll
            for (int j = 0; j < 4; j++) acc[mt][nt][j] = 0.f;

    int rowg = n0 + arow; if (rowg >= N) rowg = N - 1;

#pragma unroll 1
    for (int chunk = 0; chunk < 32; chunk++) {
        __syncthreads();
        const float* Ap = (chunk < 16) ? x : aggv;
        int kk = (chunk & 15) * 16;
        float4 v = *(const float4*)(Ap + (size_t)rowg * 256 + kk + ac4);
        sA[arow][(ac4 >> 1) + 0] = split_pack(v.x, v.y);
        sA[arow][(ac4 >> 1) + 1] = split_pack(v.z, v.w);
        const uint2* Wc = Wp + (size_t)chunk * 8 * 256;
#pragma unroll
        for (int i = 0; i < 8; i++) sB[tid][i] = Wc[i * 256 + tid];
        __syncthreads();
        uint32_t ah[2][4], al[2][4];
#pragma unroll
        for (int mt = 0; mt < 2; mt++) {
            int r = wm * 32 + mt * 16 + (lane >> 2);
            int q = lane & 3;
            uint2 v0 = sA[r][q], v1 = sA[r + 8][q];
            uint2 v2 = sA[r][q + 4], v3 = sA[r + 8][q + 4];
            ah[mt][0] = v0.x; ah[mt][1] = v1.x; ah[mt][2] = v2.x; ah[mt][3] = v3.x;
            al[mt][0] = v0.y; al[mt][1] = v1.y; al[mt][2] = v2.y; al[mt][3] = v3.y;
        }
#pragma unroll
        for (int nt = 0; nt < 8; nt++) {
            int n = wn * 64 + nt * 8 + (lane >> 2);
            uint2 b0 = sB[n][lane & 3];
            uint2 b1 = sB[n][(lane & 3) + 4];
#pragma unroll
            for (int mt = 0; mt < 2; mt++) {
                mma_bf16(acc[mt][nt], ah[mt], b0.x, b1.x);
                mma_bf16(acc[mt][nt], ah[mt], b0.y, b1.y);
                mma_bf16(acc[mt][nt], al[mt], b0.x, b1.x);
            }
        }
    }
#pragma unroll
    for (int mt = 0; mt < 2; mt++)
#pragma unroll
        for (int nt = 0; nt < 8; nt++) {
            int r0 = wm * 32 + mt * 16 + (lane >> 2);
            int c = wn * 64 + nt * 8 + 2 * (lane & 3);
            sOut[r0][c]     = acc[mt][nt][0] + sBias[c];
            sOut[r0][c + 1] = acc[mt][nt][1] + sBias[c + 1];
            sOut[r0 + 8][c]     = acc[mt][nt][2] + sBias[c];
            sOut[r0 + 8][c + 1] = acc[mt][nt][3] + sBias[c + 1];
        }
    __syncthreads();
#pragma unroll 1
    for (int i = 0; i < 8; i++) {
        int r = i * 8 + warp;
        float vv[8];
        *(float4*)&vv[0] = *(float4*)&sOut[r][lane * 4];
        *(float4*)&vv[4] = *(float4*)&sOut[r][128 + lane * 4];
        ln_silu_row(vv, lane, sG, sBv);
        int row = n0 + r;
        if (row < N) {
            float* op = tout + (size_t)row * 256;
            *(float4*)(op + lane * 4)       = make_float4(vv[0], vv[1], vv[2], vv[3]);
            *(float4*)(op + 128 + lane * 4) = make_float4(vv[4], vv[5], vv[6], vv[7]);
        }
    }
}

// ---------------------------------------------------------------------------
// Node kernel 2: out = x + t@Wn2 + b2, K = 256
// ---------------------------------------------------------------------------
__global__ __launch_bounds__(256, 2) void node2_kernel(
    const float* __restrict__ tin, const float* __restrict__ xres,
    const uint2* __restrict__ Wp, const float* __restrict__ Wb,
    float* __restrict__ out, int N) {
    extern __shared__ char smraw[];
    uint2 (*sA)[9]     = (uint2(*)[9])(smraw + SA_OFF);
    uint2 (*sB)[9]     = (uint2(*)[9])(smraw + SB_OFF);
    float (*sOut)[260] = (float(*)[260])(smraw + SOUT_OFF);
    float* sBias = (float*)(smraw + SBIAS_OFF);

    const int tid = threadIdx.x;
    const int lane = tid & 31, warp = tid >> 5;
    const int wm = warp >> 2, wn = warp & 3;
    const int n0 = blockIdx.x * 64;
    const int arow = tid >> 2, ac4 = (tid & 3) * 4;

    sBias[tid] = Wb[tid];

    float acc[2][8][4];
#pragma unroll
    for (int mt = 0; mt < 2; mt++)
#pragma unroll
        for (int nt = 0; nt < 8; nt++)
#pragma unroll
            for (int j = 0; j < 4; j++) acc[mt][nt][j] = 0.f;

    int rowg = n0 + arow; if (rowg >= N) rowg = N - 1;

#pragma unroll 1
    for (int chunk = 0; chunk < 16; chunk++) {
        __syncthreads();
        int kk = chunk * 16;
        float4 v = *(const float4*)(tin + (size_t)rowg * 256 + kk + ac4);
        sA[arow][(ac4 >> 1) + 0] = split_pack(v.x, v.y);
        sA[arow][(ac4 >> 1) + 1] = split_pack(v.z, v.w);
        const uint2* Wc = Wp + (size_t)chunk * 8 * 256;
#pragma unroll
        for (int i = 0; i < 8; i++) sB[tid][i] = Wc[i * 256 + tid];
        __syncthreads();
        uint32_t ah[2][4], al[2][4];
#pragma unroll
        for (int mt = 0; mt < 2; mt++) {
            int r = wm * 32 + mt * 16 + (lane >> 2);
            int q = lane & 3;
            uint2 v0 = sA[r][q], v1 = sA[r + 8][q];
            uint2 v2 = sA[r][q + 4], v3 = sA[r + 8][q + 4];
            ah[mt][0] = v0.x; ah[mt][1] = v1.x; ah[mt][2] = v2.x; ah[mt][3] = v3.x;
            al[mt][0] = v0.y; al[mt][1] = v1.y; al[mt][2] = v2.y; al[mt][3] = v3.y;
        }
#pragma unroll
        for (int nt = 0; nt < 8; nt++) {
            int n = wn * 64 + nt * 8 + (lane >> 2);
            uint2 b0 = sB[n][lane & 3];
            uint2 b1 = sB[n][(lane & 3) + 4];
#pragma unroll
            for (int mt = 0; mt < 2; mt++) {
                mma_bf16(acc[mt][nt], ah[mt], b0.x, b1.x);
                mma_bf16(acc[mt][nt], ah[mt], b0.y, b1.y);
                mma_bf16(acc[mt][nt], al[mt], b0.x, b1.x);
            }
        }
    }
#pragma unroll
    for (int mt = 0; mt < 2; mt++)
#pragma unroll
        for (int nt = 0; nt < 8; nt++) {
            int r0 = wm * 32 + mt * 16 + (lane >> 2);
            int c = wn * 64 + nt * 8 + 2 * (lane & 3);
            sOut[r0][c]     = acc[mt][nt][0] + sBias[c];
            sOut[r0][c + 1] = acc[mt][nt][1] + sBias[c + 1];
            sOut[r0 + 8][c]     = acc[mt][nt][2] + sBias[c];
            sOut[r0 + 8][c + 1] = acc[mt][nt][3] + sBias[c + 1];
        }
    __syncthreads();
#pragma unroll 1
    for (int i = 0; i < 8; i++) {
        int r = i * 8 + warp;
        int row = n0 + r;
        if (row < N) {
            const float* xr = xres + (size_t)row * 256;
            float4 lo = *(float4*)&sOut[r][lane * 4];
            float4 hi = *(float4*)&sOut[r][128 + lane * 4];
            float4 xlo = *(const float4*)(xr + lane * 4);
            float4 xhi = *(const float4*)(xr + 128 + lane * 4);
            lo.x += xlo.x; lo.y += xlo.y; lo.z += xlo.z; lo.w += xlo.w;
            hi.x += xhi.x; hi.y += xhi.y; hi.z += xhi.z; hi.w += xhi.w;
            float* op = out + (size_t)row * 256;
            *(float4*)(op + lane * 4) = lo;
            *(float4*)(op + 128 + lane * 4) = hi;
        }
    }
}

// ---------------------------------------------------------------------------
extern "C" void kernel_launch(void* const* d_in, const int* in_sizes, int n_in,
                              void* d_out, int out_size) {
    const float* x_in  = (const float*)d_in[0];
    const int*   eidx  = (const int*)d_in[1];
    const float* ea    = (const float*)d_in[2];
    const float* We_w  = (const float*)d_in[3];
    const float* We_b  = (const float*)d_in[4];
    const float* g1    = (const float*)d_in[5];
    const float* b1    = (const float*)d_in[6];
    const float* Wn1_w = (const float*)d_in[7];
    const float* Wn1_b = (const float*)d_in[8];
    const float* g2    = (const float*)d_in[9];
    const float* b2    = (const float*)d_in[10];
    const float* Wn2_w = (const float*)d_in[11];
    const float* Wn2_b = (const float*)d_in[12];

    const int N  = in_sizes[0] / 256;
    const int D  = in_sizes[1] / 2;
    const int NL = in_sizes[4] / 256;

    float *bufA, *bufB, *aggp, *tmpp;
    uint2 *wE, *wN1, *wN2;
    cudaGetSymbolAddress((void**)&bufA, g_bufA);
    cudaGetSymbolAddress((void**)&bufB, g_bufB);
    cudaGetSymbolAddress((void**)&aggp, g_agg);
    cudaGetSymbolAddress((void**)&tmpp, g_tmp);
    cudaGetSymbolAddress((void**)&wE,  g_We);
    cudaGetSymbolAddress((void**)&wN1, g_Wn1);
    cudaGetSymbolAddress((void**)&wN2, g_Wn2);

    cudaFuncSetAttribute(edge_kernel,  cudaFuncAttributeMaxDynamicSharedMemorySize, SMEM_BYTES);
    cudaFuncSetAttribute(node1_kernel, cudaFuncAttributeMaxDynamicSharedMemorySize, SMEM_BYTES);
    cudaFuncSetAttribute(node2_kernel, cudaFuncAttributeMaxDynamicSharedMemorySize, SMEM_BYTES);

    // pack + split weights (per launch; cheap, deterministic)
    {
        int t0 = NL * 264 * 256;
        pack_weights<<<(t0 + 255) / 256, 256>>>(We_w, wE, 516, 528, NL);
        int t1 = NL * 256 * 256;
        pack_weights<<<(t1 + 255) / 256, 256>>>(Wn1_w, wN1, 512, 512, NL);
        int t2 = NL * 128 * 256;
        pack_weights<<<(t2 + 255) / 256, 256>>>(Wn2_w, wN2, 256, 256, NL);
    }

    const int nblk_e = (D + 63) / 64;
    const int nblk_n = (N + 63) / 64;
    const int n4 = (N * 256) / 4;
    const int zblk = (n4 + 255) / 256;

    const float* xcur = x_in;
    for (int l = 0; l < NL; l++) {
        float* xnext = (l == NL - 1) ? (float*)d_out : ((l & 1) ? bufB : bufA);
        zero_kernel<<<zblk, 256>>>((float4*)aggp, n4);
        edge_kernel<<<nblk_e, 256, SMEM_BYTES>>>(
            xcur, eidx, ea, wE + (size_t)l * 264 * 256,
            We_b + (size_t)l * 256, g1 + (size_t)l * 256, b1 + (size_t)l * 256,
            aggp, D);
        node1_kernel<<<nblk_n, 256, SMEM_BYTES>>>(
            xcur, aggp, wN1 + (size_t)l * 256 * 256,
            Wn1_b + (size_t)l * 256, g2 + (size_t)l * 256, b2 + (size_t)l * 256,
            tmpp, N);
        node2_kernel<<<nblk_n, 256, SMEM_BYTES>>>(
            tmpp, xcur, wN2 + (size_t)l * 128 * 256,
            Wn2_b + (size_t)l * 256, xnext, N);
        xcur = xnext;
    }
}

// round 3
// speedup vs baseline: 2.0581x; 1.2187x over previous
#include <cuda_runtime.h>
#include <cuda_bf16.h>
#include <cstdint>

// ============================================================================
// GraphCastProcessor — split-bf16 mma.sync, cp.async double-buffered pipeline.
// Weights packed in per-lane fragment order (uint4 per lane), activations
// pre-split to uint2 {hi-pair, lo-pair}. Mainloop = pure DMA + HMMA.
// Block tile 64 rows x 256 cols, 8 warps (2 wm x 4 wn).
// ============================================================================

#define MAXN 40962
#define MAXD 163848
#define MAXNL 6

__device__ float g_bufA[MAXN * 256];
__device__ float g_bufB[MAXN * 256];
__device__ float g_agg [MAXN * 256];
// pre-split activations (uint2 = {bf16x2 hi, bf16x2 lo} per k-pair)
__device__ uint2 g_xs  [MAXN * 128];
__device__ uint2 g_aggs[MAXN * 128];
__device__ uint2 g_tmps[MAXN * 128];
__device__ uint2 g_eas [MAXD * 8];      // ea split, padded to 8 kpairs
// fragment-ordered weights: [layer][chunk][wn(4)][nt(8)][lane(32)] uint4
__device__ uint4 g_We [MAXNL * 33 * 1024];
__device__ uint4 g_Wn1[MAXNL * 32 * 1024];
__device__ uint4 g_Wn2[MAXNL * 16 * 1024];

// ---- dynamic smem layout (bytes) ----
#define SA_OFF    0                       // uint2 sA[2][64][10] = 10240
#define SB_OFF    10240                   // uint4 sB[2][1024]   = 32768 -> 43008
#define SOUT_OFF  0                       // float sOut[64][260] = 66560 (aliases)
#define SIDX_OFF  66560                   // int [128]
#define SBIAS_OFF 67072
#define SG_OFF    68096
#define SBV_OFF   69120
#define SMEM_BYTES 70144

__device__ __forceinline__ float fast_silu(float y) {
    return __fdividef(y, 1.0f + __expf(-y));
}

__device__ __forceinline__ uint2 split_pack(float a, float b) {
    __nv_bfloat16 h0 = __float2bfloat16(a);
    __nv_bfloat16 h1 = __float2bfloat16(b);
    __nv_bfloat16 l0 = __float2bfloat16(a - __bfloat162float(h0));
    __nv_bfloat16 l1 = __float2bfloat16(b - __bfloat162float(h1));
    uint2 r;
    r.x = (uint32_t)__bfloat16_as_ushort(h0) | ((uint32_t)__bfloat16_as_ushort(h1) << 16);
    r.y = (uint32_t)__bfloat16_as_ushort(l0) | ((uint32_t)__bfloat16_as_ushort(l1) << 16);
    return r;
}

__device__ __forceinline__ void mma_bf16(float c[4], const uint32_t a[4],
                                         uint32_t b0, uint32_t b1) {
    asm volatile(
        "mma.sync.aligned.m16n8k16.row.col.f32.bf16.bf16.f32 "
        "{%0,%1,%2,%3}, {%4,%5,%6,%7}, {%8,%9}, {%0,%1,%2,%3};"
        : "+f"(c[0]), "+f"(c[1]), "+f"(c[2]), "+f"(c[3])
        : "r"(a[0]), "r"(a[1]), "r"(a[2]), "r"(a[3]), "r"(b0), "r"(b1));
}

__device__ __forceinline__ void cp16(uint32_t smem_dst, const void* gsrc) {
    asm volatile("cp.async.cg.shared.global [%0], [%1], 16;\n"
                 :: "r"(smem_dst), "l"(gsrc));
}
#define CP_COMMIT() asm volatile("cp.async.commit_group;\n" ::: "memory")
#define CP_WAIT(n)  asm volatile("cp.async.wait_group %0;\n" :: "n"(n) : "memory")

// LayerNorm(256) + SiLU over one row held as 8 vals/lane across a warp.
__device__ __forceinline__ void ln_silu_row(float v[8], int tx,
                                            const float* sG, const float* sB) {
    float s = v[0] + v[1] + v[2] + v[3] + v[4] + v[5] + v[6] + v[7];
#pragma unroll
    for (int o = 16; o > 0; o >>= 1) s += __shfl_xor_sync(0xffffffffu, s, o);
    float mean = s * (1.0f / 256.0f);
    float vs = 0.f;
#pragma unroll
    for (int j = 0; j < 8; j++) { float d = v[j] - mean; vs += d * d; }
#pragma unroll
    for (int o = 16; o > 0; o >>= 1) vs += __shfl_xor_sync(0xffffffffu, vs, o);
    float rstd = rsqrtf(vs * (1.0f / 256.0f) + 1e-5f);
#pragma unroll
    for (int j = 0; j < 8; j++) {
        int col = (j < 4) ? (tx * 4 + j) : (128 + tx * 4 + j - 4);
        float y = (v[j] - mean) * rstd * sG[col] + sB[col];
        v[j] = fast_silu(y);
    }
}

// one K16 chunk of MMAs from smem buffers
__device__ __forceinline__ void compute_chunk(const char* smraw, int buf,
                                              int wm, int wn, int lane,
                                              float acc[2][8][4]) {
    const uint2* sAp = (const uint2*)(smraw + SA_OFF + buf * 5120);
    const uint4* sBp = (const uint4*)(smraw + SB_OFF + buf * 16384);
    uint32_t ah[2][4], al[2][4];
    const int q = lane & 3;
#pragma unroll
    for (int mt = 0; mt < 2; mt++) {
        int r = wm * 32 + mt * 16 + (lane >> 2);
        uint2 v0 = sAp[r * 10 + q];
        uint2 v1 = sAp[(r + 8) * 10 + q];
        uint2 v2 = sAp[r * 10 + q + 4];
        uint2 v3 = sAp[(r + 8) * 10 + q + 4];
        ah[mt][0] = v0.x; ah[mt][1] = v1.x; ah[mt][2] = v2.x; ah[mt][3] = v3.x;
        al[mt][0] = v0.y; al[mt][1] = v1.y; al[mt][2] = v2.y; al[mt][3] = v3.y;
    }
#pragma unroll
    for (int nt = 0; nt < 8; nt++) {
        uint4 b = sBp[wn * 256 + nt * 32 + lane];
#pragma unroll
        for (int mt = 0; mt < 2; mt++) {
            mma_bf16(acc[mt][nt], ah[mt], b.x, b.y);  // hi*hi
            mma_bf16(acc[mt][nt], ah[mt], b.z, b.w);  // hi*lo
            mma_bf16(acc[mt][nt], al[mt], b.x, b.y);  // lo*hi
        }
    }
}

__device__ __forceinline__ void acc_to_sout(const char* smraw, int wm, int wn,
                                            int lane, float acc[2][8][4],
                                            const float* sBias) {
    float (*sOut)[260] = (float(*)[260])((char*)smraw + SOUT_OFF);
#pragma unroll
    for (int mt = 0; mt < 2; mt++)
#pragma unroll
        for (int nt = 0; nt < 8; nt++) {
            int r0 = wm * 32 + mt * 16 + (lane >> 2);
            int c = wn * 64 + nt * 8 + 2 * (lane & 3);
            sOut[r0][c]         = acc[mt][nt][0] + sBias[c];
            sOut[r0][c + 1]     = acc[mt][nt][1] + sBias[c + 1];
            sOut[r0 + 8][c]     = acc[mt][nt][2] + sBias[c];
            sOut[r0 + 8][c + 1] = acc[mt][nt][3] + sBias[c + 1];
        }
}

// ---------------------------------------------------------------------------
// packers / converters
// ---------------------------------------------------------------------------
__global__ void pack_w_frag(const float* __restrict__ W, uint4* __restrict__ out,
                            int Ksrc, int C, int NL) {
    size_t idx = (size_t)blockIdx.x * blockDim.x + threadIdx.x;
    size_t total = (size_t)NL * C * 1024;
    if (idx >= total) return;
    int t = (int)(idx & 1023);
    int lane = t & 31, nt = (t >> 5) & 7, wn = t >> 8;
    int c = (int)((idx >> 10) % C);
    int l = (int)(idx / ((size_t)C * 1024));
    int n = wn * 64 + nt * 8 + (lane >> 2);
    int q = lane & 3;
    int kp0 = c * 8 + q, kp1 = c * 8 + q + 4;
    const float* Wl = W + (size_t)l * Ksrc * 256;
    float a0 = (2 * kp0     < Ksrc) ? Wl[(size_t)(2 * kp0)     * 256 + n] : 0.f;
    float a1 = (2 * kp0 + 1 < Ksrc) ? Wl[(size_t)(2 * kp0 + 1) * 256 + n] : 0.f;
    float b0 = (2 * kp1     < Ksrc) ? Wl[(size_t)(2 * kp1)     * 256 + n] : 0.f;
    float b1 = (2 * kp1 + 1 < Ksrc) ? Wl[(size_t)(2 * kp1 + 1) * 256 + n] : 0.f;
    uint2 p0 = split_pack(a0, a1);
    uint2 p1 = split_pack(b0, b1);
    out[idx] = make_uint4(p0.x, p1.x, p0.y, p1.y);
}

__global__ void convert_split(const float* __restrict__ in, uint2* __restrict__ out,
                              int n) {  // n = M*128
    int i = blockIdx.x * blockDim.x + threadIdx.x;
    if (i < n) {
        float2 v = ((const float2*)in)[i];
        out[i] = split_pack(v.x, v.y);
    }
}

__global__ void pack_ea(const float* __restrict__ ea, uint2* __restrict__ out, int D) {
    int e = blockIdx.x * blockDim.x + threadIdx.x;
    if (e >= D) return;
    const float* p = ea + (size_t)e * 4;
    uint2* o = out + (size_t)e * 8;
    o[0] = split_pack(p[0], p[1]);
    o[1] = split_pack(p[2], p[3]);
    uint2 z = make_uint2(0u, 0u);
#pragma unroll
    for (int i = 2; i < 8; i++) o[i] = z;
}

__global__ void zero_kernel(float4* __restrict__ p, int n4) {
    int i = blockIdx.x * blockDim.x + threadIdx.x;
    if (i < n4) p[i] = make_float4(0.f, 0.f, 0.f, 0.f);
}

// ---------------------------------------------------------------------------
// Edge kernel: 64 edges/block, 33 chunks (dst:16, src:16, ea:1)
// ---------------------------------------------------------------------------
__global__ __launch_bounds__(256, 2) void edge_kernel(
    const uint2* __restrict__ xs, const int* __restrict__ eidx,
    const uint2* __restrict__ eas, const uint4* __restrict__ Wp,
    const float* __restrict__ Wb, const float* __restrict__ gam,
    const float* __restrict__ bet, float* __restrict__ agg, int D) {
    extern __shared__ char smraw[];
    int*   sIdx  = (int*)(smraw + SIDX_OFF);
    float* sBias = (float*)(smraw + SBIAS_OFF);
    float* sG    = (float*)(smraw + SG_OFF);
    float* sBv   = (float*)(smraw + SBV_OFF);

    const int tid = threadIdx.x;
    const int lane = tid & 31, warp = tid >> 5;
    const int wm = warp >> 2, wn = warp & 3;
    const int e0 = blockIdx.x * 64;
    const uint32_t sbase = (uint32_t)__cvta_generic_to_shared(smraw);
    const int arow = tid >> 2, apart = tid & 3;

    if (tid < 128) {
        int p = tid >> 6, r = tid & 63;
        int e = e0 + r; if (e >= D) e = D - 1;
        sIdx[p * 64 + r] = eidx[(size_t)p * D + e];
    }
    sBias[tid] = Wb[tid]; sG[tid] = gam[tid]; sBv[tid] = bet[tid];
    __syncthreads();

    auto stageA = [&](int c, int buf) {
        const uint2* src;
        if (c < 16)      src = xs + (size_t)sIdx[64 + arow] * 128 + c * 8;
        else if (c < 32) src = xs + (size_t)sIdx[arow] * 128 + (c - 16) * 8;
        else {
            int e = e0 + arow; if (e >= D) e = D - 1;
            src = eas + (size_t)e * 8;
        }
        cp16(sbase + SA_OFF + buf * 5120 + arow * 80 + apart * 16,
             (const char*)src + apart * 16);
    };
    auto stageB = [&](int c, int buf) {
        const uint4* Wc = Wp + (size_t)c * 1024;
        uint32_t d = sbase + SB_OFF + buf * 16384 + tid * 16;
        cp16(d,         Wc + tid);
        cp16(d + 4096,  Wc + tid + 256);
        cp16(d + 8192,  Wc + tid + 512);
        cp16(d + 12288, Wc + tid + 768);
    };

    float acc[2][8][4];
#pragma unroll
    for (int mt = 0; mt < 2; mt++)
#pragma unroll
        for (int nt = 0; nt < 8; nt++)
#pragma unroll
            for (int j = 0; j < 4; j++) acc[mt][nt][j] = 0.f;

    stageA(0, 0); stageB(0, 0); CP_COMMIT();
#pragma unroll 1
    for (int c = 0; c < 33; c++) {
        if (c + 1 < 33) {
            stageA(c + 1, (c + 1) & 1); stageB(c + 1, (c + 1) & 1);
            CP_COMMIT(); CP_WAIT(1);
        } else {
            CP_WAIT(0);
        }
        __syncthreads();
        compute_chunk(smraw, c & 1, wm, wn, lane, acc);
        __syncthreads();
    }

    acc_to_sout(smraw, wm, wn, lane, acc, sBias);
    __syncthreads();
    float (*sOut)[260] = (float(*)[260])(smraw + SOUT_OFF);
#pragma unroll 1
    for (int i = 0; i < 8; i++) {
        int r = i * 8 + warp;
        float vv[8];
        *(float4*)&vv[0] = *(float4*)&sOut[r][lane * 4];
        *(float4*)&vv[4] = *(float4*)&sOut[r][128 + lane * 4];
        ln_silu_row(vv, lane, sG, sBv);
        int e = e0 + r;
        if (e < D) {
            float* ag = agg + (size_t)sIdx[64 + r] * 256;
#pragma unroll
            for (int j = 0; j < 8; j++) {
                int col = (j < 4) ? (lane * 4 + j) : (128 + lane * 4 + j - 4);
                atomicAdd(ag + col, vv[j]);
            }
        }
    }
}

// ---------------------------------------------------------------------------
// Node kernel 1: t = silu(LN(x@Wn1[:256] + agg@Wn1[256:] + b)) -> tmps (split)
// ---------------------------------------------------------------------------
__global__ __launch_bounds__(256, 2) void node1_kernel(
    const uint2* __restrict__ xs, const uint2* __restrict__ aggs,
    const uint4* __restrict__ Wp, const float* __restrict__ Wb,
    const float* __restrict__ gam, const float* __restrict__ bet,
    uint2* __restrict__ tmps, int N) {
    extern __shared__ char smraw[];
    float* sBias = (float*)(smraw + SBIAS_OFF);
    float* sG    = (float*)(smraw + SG_OFF);
    float* sBv   = (float*)(smraw + SBV_OFF);

    const int tid = threadIdx.x;
    const int lane = tid & 31, warp = tid >> 5;
    const int wm = warp >> 2, wn = warp & 3;
    const int n0 = blockIdx.x * 64;
    const uint32_t sbase = (uint32_t)__cvta_generic_to_shared(smraw);
    const int arow = tid >> 2, apart = tid & 3;

    sBias[tid] = Wb[tid]; sG[tid] = gam[tid]; sBv[tid] = bet[tid];
    __syncthreads();

    int rowg = n0 + arow; if (rowg >= N) rowg = N - 1;

    auto stageA = [&](int c, int buf) {
        const uint2* src = (c < 16 ? xs : aggs) + (size_t)rowg * 128 + (c & 15) * 8;
        cp16(sbase + SA_OFF + buf * 5120 + arow * 80 + apart * 16,
             (const char*)src + apart * 16);
    };
    auto stageB = [&](int c, int buf) {
        const uint4* Wc = Wp + (size_t)c * 1024;
        uint32_t d = sbase + SB_OFF + buf * 16384 + tid * 16;
        cp16(d,         Wc + tid);
        cp16(d + 4096,  Wc + tid + 256);
        cp16(d + 8192,  Wc + tid + 512);
        cp16(d + 12288, Wc + tid + 768);
    };

    float acc[2][8][4];
#pragma unroll
    for (int mt = 0; mt < 2; mt++)
#pragma unroll
        for (int nt = 0; nt < 8; nt++)
#pragma unroll
            for (int j = 0; j < 4; j++) acc[mt][nt][j] = 0.f;

    stageA(0, 0); stageB(0, 0); CP_COMMIT();
#pragma unroll 1
    for (int c = 0; c < 32; c++) {
        if (c + 1 < 32) {
            stageA(c + 1, (c + 1) & 1); stageB(c + 1, (c + 1) & 1);
            CP_COMMIT(); CP_WAIT(1);
        } else {
            CP_WAIT(0);
        }
        __syncthreads();
        compute_chunk(smraw, c & 1, wm, wn, lane, acc);
        __syncthreads();
    }

    acc_to_sout(smraw, wm, wn, lane, acc, sBias);
    __syncthreads();
    float (*sOut)[260] = (float(*)[260])(smraw + SOUT_OFF);
#pragma unroll 1
    for (int i = 0; i < 8; i++) {
        int r = i * 8 + warp;
        float vv[8];
        *(float4*)&vv[0] = *(float4*)&sOut[r][lane * 4];
        *(float4*)&vv[4] = *(float4*)&sOut[r][128 + lane * 4];
        ln_silu_row(vv, lane, sG, sBv);
        int row = n0 + r;
        if (row < N) {
            uint2* op = tmps + (size_t)row * 128;
            op[lane * 2]          = split_pack(vv[0], vv[1]);
            op[lane * 2 + 1]      = split_pack(vv[2], vv[3]);
            op[64 + lane * 2]     = split_pack(vv[4], vv[5]);
            op[64 + lane * 2 + 1] = split_pack(vv[6], vv[7]);
        }
    }
}

// ---------------------------------------------------------------------------
// Node kernel 2: out = x + t@Wn2 + b2 (fp32) ; also writes xs split for next layer
// ---------------------------------------------------------------------------
__global__ __launch_bounds__(256, 2) void node2_kernel(
    const uint2* __restrict__ tmps, const float* __restrict__ xres,
    const uint4* __restrict__ Wp, const float* __restrict__ Wb,
    float* __restrict__ out, uint2* __restrict__ xs_next, int N) {
    extern __shared__ char smraw[];
    float* sBias = (float*)(smraw + SBIAS_OFF);

    const int tid = threadIdx.x;
    const int lane = tid & 31, warp = tid >> 5;
    const int wm = warp >> 2, wn = warp & 3;
    const int n0 = blockIdx.x * 64;
    const uint32_t sbase = (uint32_t)__cvta_generic_to_shared(smraw);
    const int arow = tid >> 2, apart = tid & 3;

    sBias[tid] = Wb[tid];
    __syncthreads();

    int rowg = n0 + arow; if (rowg >= N) rowg = N - 1;

    auto stageA = [&](int c, int buf) {
        const uint2* src = tmps + (size_t)rowg * 128 + c * 8;
        cp16(sbase + SA_OFF + buf * 5120 + arow * 80 + apart * 16,
             (const char*)src + apart * 16);
    };
    auto stageB = [&](int c, int buf) {
        const uint4* Wc = Wp + (size_t)c * 1024;
        uint32_t d = sbase + SB_OFF + buf * 16384 + tid * 16;
        cp16(d,         Wc + tid);
        cp16(d + 4096,  Wc + tid + 256);
        cp16(d + 8192,  Wc + tid + 512);
        cp16(d + 12288, Wc + tid + 768);
    };

    float acc[2][8][4];
#pragma unroll
    for (int mt = 0; mt < 2; mt++)
#pragma unroll
        for (int nt = 0; nt < 8; nt++)
#pragma unroll
            for (int j = 0; j < 4; j++) acc[mt][nt][j] = 0.f;

    stageA(0, 0); stageB(0, 0); CP_COMMIT();
#pragma unroll 1
    for (int c = 0; c < 16; c++) {
        if (c + 1 < 16) {
            stageA(c + 1, (c + 1) & 1); stageB(c + 1, (c + 1) & 1);
            CP_COMMIT(); CP_WAIT(1);
        } else {
            CP_WAIT(0);
        }
        __syncthreads();
        compute_chunk(smraw, c & 1, wm, wn, lane, acc);
        __syncthreads();
    }

    acc_to_sout(smraw, wm, wn, lane, acc, sBias);
    __syncthreads();
    float (*sOut)[260] = (float(*)[260])(smraw + SOUT_OFF);
#pragma unroll 1
    for (int i = 0; i < 8; i++) {
        int r = i * 8 + warp;
        int row = n0 + r;
        if (row < N) {
            const float* xr = xres + (size_t)row * 256;
            float4 lo = *(float4*)&sOut[r][lane * 4];
            float4 hi = *(float4*)&sOut[r][128 + lane * 4];
            float4 xlo = *(const float4*)(xr + lane * 4);
            float4 xhi = *(const float4*)(xr + 128 + lane * 4);
            lo.x += xlo.x; lo.y += xlo.y; lo.z += xlo.z; lo.w += xlo.w;
            hi.x += xhi.x; hi.y += xhi.y; hi.z += xhi.z; hi.w += xhi.w;
            float* op = out + (size_t)row * 256;
            *(float4*)(op + lane * 4) = lo;
            *(float4*)(op + 128 + lane * 4) = hi;
            uint2* xp = xs_next + (size_t)row * 128;
            xp[lane * 2]          = split_pack(lo.x, lo.y);
            xp[lane * 2 + 1]      = split_pack(lo.z, lo.w);
            xp[64 + lane * 2]     = split_pack(hi.x, hi.y);
            xp[64 + lane * 2 + 1] = split_pack(hi.z, hi.w);
        }
    }
}

// ---------------------------------------------------------------------------
extern "C" void kernel_launch(void* const* d_in, const int* in_sizes, int n_in,
                              void* d_out, int out_size) {
    const float* x_in  = (const float*)d_in[0];
    const int*   eidx  = (const int*)d_in[1];
    const float* ea    = (const float*)d_in[2];
    const float* We_w  = (const float*)d_in[3];
    const float* We_b  = (const float*)d_in[4];
    const float* g1    = (const float*)d_in[5];
    const float* b1    = (const float*)d_in[6];
    const float* Wn1_w = (const float*)d_in[7];
    const float* Wn1_b = (const float*)d_in[8];
    const float* g2    = (const float*)d_in[9];
    const float* b2    = (const float*)d_in[10];
    const float* Wn2_w = (const float*)d_in[11];
    const float* Wn2_b = (const float*)d_in[12];

    const int N  = in_sizes[0] / 256;
    const int D  = in_sizes[1] / 2;
    const int NL = in_sizes[4] / 256;

    float *bufA, *bufB, *aggp;
    uint2 *xs, *aggs, *tmps, *eas;
    uint4 *wE, *wN1, *wN2;
    cudaGetSymbolAddress((void**)&bufA, g_bufA);
    cudaGetSymbolAddress((void**)&bufB, g_bufB);
    cudaGetSymbolAddress((void**)&aggp, g_agg);
    cudaGetSymbolAddress((void**)&xs,   g_xs);
    cudaGetSymbolAddress((void**)&aggs, g_aggs);
    cudaGetSymbolAddress((void**)&tmps, g_tmps);
    cudaGetSymbolAddress((void**)&eas,  g_eas);
    cudaGetSymbolAddress((void**)&wE,   g_We);
    cudaGetSymbolAddress((void**)&wN1,  g_Wn1);
    cudaGetSymbolAddress((void**)&wN2,  g_Wn2);

    cudaFuncSetAttribute(edge_kernel,  cudaFuncAttributeMaxDynamicSharedMemorySize, SMEM_BYTES);
    cudaFuncSetAttribute(node1_kernel, cudaFuncAttributeMaxDynamicSharedMemorySize, SMEM_BYTES);
    cudaFuncSetAttribute(node2_kernel, cudaFuncAttributeMaxDynamicSharedMemorySize, SMEM_BYTES);

    // one-time packs (inside capture; deterministic)
    {
        size_t t0 = (size_t)NL * 33 * 1024;
        pack_w_frag<<<(int)((t0 + 255) / 256), 256>>>(We_w, wE, 516, 33, NL);
        size_t t1 = (size_t)NL * 32 * 1024;
        pack_w_frag<<<(int)((t1 + 255) / 256), 256>>>(Wn1_w, wN1, 512, 32, NL);
        size_t t2 = (size_t)NL * 16 * 1024;
        pack_w_frag<<<(int)((t2 + 255) / 256), 256>>>(Wn2_w, wN2, 256, 16, NL);
        pack_ea<<<(D + 255) / 256, 256>>>(ea, eas, D);
        int nx = N * 128;
        convert_split<<<(nx + 255) / 256, 256>>>(x_in, xs, nx);
    }

    const int nblk_e = (D + 63) / 64;
    const int nblk_n = (N + 63) / 64;
    const int n4 = (N * 256) / 4;
    const int zblk = (n4 + 255) / 256;
    const int ncv = N * 128;
    const int cvblk = (ncv + 255) / 256;

    const float* xcur = x_in;
    for (int l = 0; l < NL; l++) {
        float* xnext = (l == NL - 1) ? (float*)d_out : ((l & 1) ? bufB : bufA);
        zero_kernel<<<zblk, 256>>>((float4*)aggp, n4);
        edge_kernel<<<nblk_e, 256, SMEM_BYTES>>>(
            xs, eidx, eas, wE + (size_t)l * 33 * 1024,
            We_b + (size_t)l * 256, g1 + (size_t)l * 256, b1 + (size_t)l * 256,
            aggp, D);
        convert_split<<<cvblk, 256>>>(aggp, aggs, ncv);
        node1_kernel<<<nblk_n, 256, SMEM_BYTES>>>(
            xs, aggs, wN1 + (size_t)l * 32 * 1024,
            Wn1_b + (size_t)l * 256, g2 + (size_t)l * 256, b2 + (size_t)l * 256,
            tmps, N);
        node2_kernel<<<nblk_n, 256, SMEM_BYTES>>>(
            tmps, xcur, wN2 + (size_t)l * 16 * 1024,
            Wn2_b + (size_t)l * 256, xnext, xs, N);
        xcur = xnext;
    }
}

// round 4
// speedup vs baseline: 2.7898x; 1.3555x over previous
#include <cuda_runtime.h>
#include <cuda_bf16.h>
#include <cstdint>

// ============================================================================
// GraphCastProcessor — restructured: dense node GEMMs + memory-only edge pass.
// Per layer:
//   y1 = x@We[:256], y2 = x@We[256:512]              (dense split-bf16 GEMMs)
//   h_e = y1[dst] + y2[src] + ea@We[512:516] + be    (edge pass, SIMT)
//   msg = silu(LN(h)); agg += msg  (atomicAdd)
//   u = x@Wn1[:256] + agg@Wn1[256:] + b; t = silu(LN(u))
//   x = x + t@Wn2 + b2
// GEMMs: mma.sync m16n8k16 bf16 2-way split (3 MMAs), cp.async double-buffer,
// fragment-ordered weights. 64x256 block tile, 8 warps.
// ============================================================================

#define MAXN 40962
#define MAXD 163848
#define MAXNL 6

__device__ float g_bufA[MAXN * 256];
__device__ float g_bufB[MAXN * 256];
__device__ float g_agg [MAXN * 256];
__device__ float g_y1  [MAXN * 256];
__device__ float g_y2  [MAXN * 256];
__device__ uint2 g_xs  [MAXN * 128];   // split activations {hi-pair, lo-pair}
__device__ uint2 g_aggs[MAXN * 128];
__device__ uint2 g_tmps[MAXN * 128];
// fragment-ordered weights: [layer][chunk][wn(4)][nt(8)][lane(32)] uint4
__device__ uint4 g_We [MAXNL * 32 * 1024];   // rows 0..511 of We
__device__ uint4 g_Wn1[MAXNL * 32 * 1024];
__device__ uint4 g_Wn2[MAXNL * 16 * 1024];

// ---- dynamic smem layout (bytes) ----
#define SA_OFF    0                       // uint2 sA[2][64][10] = 10240
#define SB_OFF    10240                   // uint4 sB[2][1024]   -> 43008
#define SOUT_OFF  0                       // float sOut[64][260] = 66560 (aliases)
#define SBIAS_OFF 66560
#define SG_OFF    67584
#define SBV_OFF   68608
#define SMEM_BYTES 69632

__device__ __forceinline__ float fast_silu(float y) {
    return __fdividef(y, 1.0f + __expf(-y));
}

__device__ __forceinline__ uint2 split_pack(float a, float b) {
    __nv_bfloat16 h0 = __float2bfloat16(a);
    __nv_bfloat16 h1 = __float2bfloat16(b);
    __nv_bfloat16 l0 = __float2bfloat16(a - __bfloat162float(h0));
    __nv_bfloat16 l1 = __float2bfloat16(b - __bfloat162float(h1));
    uint2 r;
    r.x = (uint32_t)__bfloat16_as_ushort(h0) | ((uint32_t)__bfloat16_as_ushort(h1) << 16);
    r.y = (uint32_t)__bfloat16_as_ushort(l0) | ((uint32_t)__bfloat16_as_ushort(l1) << 16);
    return r;
}

__device__ __forceinline__ void mma_bf16(float c[4], const uint32_t a[4],
                                         uint32_t b0, uint32_t b1) {
    asm volatile(
        "mma.sync.aligned.m16n8k16.row.col.f32.bf16.bf16.f32 "
        "{%0,%1,%2,%3}, {%4,%5,%6,%7}, {%8,%9}, {%0,%1,%2,%3};"
        : "+f"(c[0]), "+f"(c[1]), "+f"(c[2]), "+f"(c[3])
        : "r"(a[0]), "r"(a[1]), "r"(a[2]), "r"(a[3]), "r"(b0), "r"(b1));
}

__device__ __forceinline__ void cp16(uint32_t smem_dst, const void* gsrc) {
    asm volatile("cp.async.cg.shared.global [%0], [%1], 16;\n"
                 :: "r"(smem_dst), "l"(gsrc));
}
#define CP_COMMIT() asm volatile("cp.async.commit_group;\n" ::: "memory")
#define CP_WAIT(n)  asm volatile("cp.async.wait_group %0;\n" :: "n"(n) : "memory")

// LN(256)+SiLU; row spread as 8 vals/lane (cols lane*4+j / 128+lane*4+j-4)
__device__ __forceinline__ void ln_silu_row(float v[8], int tx,
                                            const float* sG, const float* sB) {
    float s = v[0] + v[1] + v[2] + v[3] + v[4] + v[5] + v[6] + v[7];
#pragma unroll
    for (int o = 16; o > 0; o >>= 1) s += __shfl_xor_sync(0xffffffffu, s, o);
    float mean = s * (1.0f / 256.0f);
    float vs = 0.f;
#pragma unroll
    for (int j = 0; j < 8; j++) { float d = v[j] - mean; vs += d * d; }
#pragma unroll
    for (int o = 16; o > 0; o >>= 1) vs += __shfl_xor_sync(0xffffffffu, vs, o);
    float rstd = rsqrtf(vs * (1.0f / 256.0f) + 1e-5f);
#pragma unroll
    for (int j = 0; j < 8; j++) {
        int col = (j < 4) ? (tx * 4 + j) : (128 + tx * 4 + j - 4);
        float y = (v[j] - mean) * rstd * sG[col] + sB[col];
        v[j] = fast_silu(y);
    }
}

__device__ __forceinline__ void compute_chunk(const char* smraw, int buf,
                                              int wm, int wn, int lane,
                                              float acc[2][8][4]) {
    const uint2* sAp = (const uint2*)(smraw + SA_OFF + buf * 5120);
    const uint4* sBp = (const uint4*)(smraw + SB_OFF + buf * 16384);
    uint32_t ah[2][4], al[2][4];
    const int q = lane & 3;
#pragma unroll
    for (int mt = 0; mt < 2; mt++) {
        int r = wm * 32 + mt * 16 + (lane >> 2);
        uint2 v0 = sAp[r * 10 + q];
        uint2 v1 = sAp[(r + 8) * 10 + q];
        uint2 v2 = sAp[r * 10 + q + 4];
        uint2 v3 = sAp[(r + 8) * 10 + q + 4];
        ah[mt][0] = v0.x; ah[mt][1] = v1.x; ah[mt][2] = v2.x; ah[mt][3] = v3.x;
        al[mt][0] = v0.y; al[mt][1] = v1.y; al[mt][2] = v2.y; al[mt][3] = v3.y;
    }
#pragma unroll
    for (int nt = 0; nt < 8; nt++) {
        uint4 b = sBp[wn * 256 + nt * 32 + lane];
#pragma unroll
        for (int mt = 0; mt < 2; mt++) {
            mma_bf16(acc[mt][nt], ah[mt], b.x, b.y);
            mma_bf16(acc[mt][nt], ah[mt], b.z, b.w);
            mma_bf16(acc[mt][nt], al[mt], b.x, b.y);
        }
    }
}

template <typename FA>
__device__ __forceinline__ void gemm_pipeline(FA stageA, const uint4* __restrict__ Wp,
                                              char* smraw, uint32_t sbase, int tid,
                                              int wm, int wn, int lane, int chunks,
                                              float acc[2][8][4]) {
    auto stageB = [&](int c, int buf) {
        const uint4* Wc = Wp + (size_t)c * 1024;
        uint32_t d = sbase + SB_OFF + buf * 16384 + tid * 16;
        cp16(d,         Wc + tid);
        cp16(d + 4096,  Wc + tid + 256);
        cp16(d + 8192,  Wc + tid + 512);
        cp16(d + 12288, Wc + tid + 768);
    };
    stageA(0, 0); stageB(0, 0); CP_COMMIT();
#pragma unroll 1
    for (int c = 0; c < chunks; c++) {
        if (c + 1 < chunks) {
            stageA(c + 1, (c + 1) & 1); stageB(c + 1, (c + 1) & 1);
            CP_COMMIT(); CP_WAIT(1);
        } else {
            CP_WAIT(0);
        }
        __syncthreads();
        compute_chunk(smraw, c & 1, wm, wn, lane, acc);
        __syncthreads();
    }
}

__device__ __forceinline__ void acc_to_sout(char* smraw, int wm, int wn,
                                            int lane, float acc[2][8][4],
                                            const float* sBias) {
    float (*sOut)[260] = (float(*)[260])(smraw + SOUT_OFF);
#pragma unroll
    for (int mt = 0; mt < 2; mt++)
#pragma unroll
        for (int nt = 0; nt < 8; nt++) {
            int r0 = wm * 32 + mt * 16 + (lane >> 2);
            int c = wn * 64 + nt * 8 + 2 * (lane & 3);
            float b0 = sBias ? sBias[c] : 0.f;
            float b1 = sBias ? sBias[c + 1] : 0.f;
            sOut[r0][c]         = acc[mt][nt][0] + b0;
            sOut[r0][c + 1]     = acc[mt][nt][1] + b1;
            sOut[r0 + 8][c]     = acc[mt][nt][2] + b0;
            sOut[r0 + 8][c + 1] = acc[mt][nt][3] + b1;
        }
}

// ---------------------------------------------------------------------------
// packers
// ---------------------------------------------------------------------------
__global__ void pack_w_frag(const float* __restrict__ W, uint4* __restrict__ out,
                            int Ksrc, int lstride, int C, int NL) {
    size_t idx = (size_t)blockIdx.x * blockDim.x + threadIdx.x;
    size_t total = (size_t)NL * C * 1024;
    if (idx >= total) return;
    int t = (int)(idx & 1023);
    int lane = t & 31, nt = (t >> 5) & 7, wn = t >> 8;
    int c = (int)((idx >> 10) % C);
    int l = (int)(idx / ((size_t)C * 1024));
    int n = wn * 64 + nt * 8 + (lane >> 2);
    int q = lane & 3;
    int kp0 = c * 8 + q, kp1 = c * 8 + q + 4;
    const float* Wl = W + (size_t)l * lstride * 256;
    float a0 = (2 * kp0     < Ksrc) ? Wl[(size_t)(2 * kp0)     * 256 + n] : 0.f;
    float a1 = (2 * kp0 + 1 < Ksrc) ? Wl[(size_t)(2 * kp0 + 1) * 256 + n] : 0.f;
    float b0 = (2 * kp1     < Ksrc) ? Wl[(size_t)(2 * kp1)     * 256 + n] : 0.f;
    float b1 = (2 * kp1 + 1 < Ksrc) ? Wl[(size_t)(2 * kp1 + 1) * 256 + n] : 0.f;
    uint2 p0 = split_pack(a0, a1);
    uint2 p1 = split_pack(b0, b1);
    out[idx] = make_uint4(p0.x, p1.x, p0.y, p1.y);
}

__global__ void convert_split(const float* __restrict__ in, uint2* __restrict__ out,
                              int n) {
    int i = blockIdx.x * blockDim.x + threadIdx.x;
    if (i < n) {
        float2 v = ((const float2*)in)[i];
        out[i] = split_pack(v.x, v.y);
    }
}

__global__ void zero_kernel(float4* __restrict__ p, int n4) {
    int i = blockIdx.x * blockDim.x + threadIdx.x;
    if (i < n4) p[i] = make_float4(0.f, 0.f, 0.f, 0.f);
}

// ---------------------------------------------------------------------------
// y12 kernel: y = x @ We[half*256 : half*256+256]  (no bias), grid.y = half
// ---------------------------------------------------------------------------
__global__ __launch_bounds__(256, 2) void y12_kernel(
    const uint2* __restrict__ xs, const uint4* __restrict__ WpBase,
    float* __restrict__ y1, float* __restrict__ y2, int N) {
    extern __shared__ char smraw[];
    const int tid = threadIdx.x;
    const int lane = tid & 31, warp = tid >> 5;
    const int wm = warp >> 2, wn = warp & 3;
    const int n0 = blockIdx.x * 64;
    const int half = blockIdx.y;
    const uint32_t sbase = (uint32_t)__cvta_generic_to_shared(smraw);
    const int arow = tid >> 2, apart = tid & 3;
    int rowg = n0 + arow; if (rowg >= N) rowg = N - 1;

    const uint4* Wp = WpBase + (size_t)half * 16 * 1024;
    float* yout = half ? y2 : y1;

    float acc[2][8][4];
#pragma unroll
    for (int mt = 0; mt < 2; mt++)
#pragma unroll
        for (int nt = 0; nt < 8; nt++)
#pragma unroll
            for (int j = 0; j < 4; j++) acc[mt][nt][j] = 0.f;

    auto stageA = [&](int c, int buf) {
        const uint2* src = xs + (size_t)rowg * 128 + c * 8;
        cp16(sbase + SA_OFF + buf * 5120 + arow * 80 + apart * 16,
             (const char*)src + apart * 16);
    };
    gemm_pipeline(stageA, Wp, smraw, sbase, tid, wm, wn, lane, 16, acc);

    acc_to_sout(smraw, wm, wn, lane, acc, nullptr);
    __syncthreads();
    float (*sOut)[260] = (float(*)[260])(smraw + SOUT_OFF);
#pragma unroll 1
    for (int i = 0; i < 8; i++) {
        int r = i * 8 + warp;
        int row = n0 + r;
        if (row < N) {
            float* op = yout + (size_t)row * 256;
            *(float4*)(op + lane * 4)       = *(float4*)&sOut[r][lane * 4];
            *(float4*)(op + 128 + lane * 4) = *(float4*)&sOut[r][128 + lane * 4];
        }
    }
}

// ---------------------------------------------------------------------------
// Edge pass (memory-bound): h = y1[dst]+y2[src]+ea@W3+b; silu(LN(h)) -> atomic agg
// one edge per warp, 8 edges per block
// ---------------------------------------------------------------------------
__global__ __launch_bounds__(256) void edge_pass(
    const float* __restrict__ y1, const float* __restrict__ y2,
    const int* __restrict__ eidx, const float* __restrict__ ea,
    const float* __restrict__ W3, const float* __restrict__ Wb,
    const float* __restrict__ gam, const float* __restrict__ bet,
    float* __restrict__ agg, int D) {
    const int tid = threadIdx.x;
    const int lane = tid & 31, warp = tid >> 5;
    const int e = blockIdx.x * 8 + warp;

    // per-lane constants for its 8 columns
    float w3r[4][8], biasr[8], gr[8], br[8];
#pragma unroll
    for (int j = 0; j < 8; j++) {
        int col = (j < 4) ? (lane * 4 + j) : (128 + lane * 4 + j - 4);
        biasr[j] = __ldg(Wb + col);
        gr[j] = __ldg(gam + col);
        br[j] = __ldg(bet + col);
#pragma unroll
        for (int k = 0; k < 4; k++) w3r[k][j] = __ldg(W3 + k * 256 + col);
    }
    if (e >= D) return;

    int src = __ldg(eidx + e);
    int dst = __ldg(eidx + (size_t)D + e);
    const float* p1 = y1 + (size_t)dst * 256;
    const float* p2 = y2 + (size_t)src * 256;
    float4 a0 = *(const float4*)(p1 + lane * 4);
    float4 a1 = *(const float4*)(p1 + 128 + lane * 4);
    float4 c0 = *(const float4*)(p2 + lane * 4);
    float4 c1 = *(const float4*)(p2 + 128 + lane * 4);
    float4 eav = *(const float4*)(ea + (size_t)e * 4);

    float v[8];
    v[0] = a0.x + c0.x; v[1] = a0.y + c0.y; v[2] = a0.z + c0.z; v[3] = a0.w + c0.w;
    v[4] = a1.x + c1.x; v[5] = a1.y + c1.y; v[6] = a1.z + c1.z; v[7] = a1.w + c1.w;
#pragma unroll
    for (int j = 0; j < 8; j++) {
        float h = v[j] + biasr[j];
        h = fmaf(eav.x, w3r[0][j], h);
        h = fmaf(eav.y, w3r[1][j], h);
        h = fmaf(eav.z, w3r[2][j], h);
        h = fmaf(eav.w, w3r[3][j], h);
        v[j] = h;
    }
    // LN + SiLU (warp reduce)
    float s = v[0] + v[1] + v[2] + v[3] + v[4] + v[5] + v[6] + v[7];
#pragma unroll
    for (int o = 16; o > 0; o >>= 1) s += __shfl_xor_sync(0xffffffffu, s, o);
    float mean = s * (1.0f / 256.0f);
    float vs = 0.f;
#pragma unroll
    for (int j = 0; j < 8; j++) { float d = v[j] - mean; vs += d * d; }
#pragma unroll
    for (int o = 16; o > 0; o >>= 1) vs += __shfl_xor_sync(0xffffffffu, vs, o);
    float rstd = rsqrtf(vs * (1.0f / 256.0f) + 1e-5f);

    float* ag = agg + (size_t)dst * 256;
#pragma unroll
    for (int j = 0; j < 8; j++) {
        int col = (j < 4) ? (lane * 4 + j) : (128 + lane * 4 + j - 4);
        float y = (v[j] - mean) * rstd * gr[j] + br[j];
        atomicAdd(ag + col, fast_silu(y));
    }
}

// ---------------------------------------------------------------------------
// Node kernel 1: t = silu(LN(x@Wn1[:256] + agg@Wn1[256:] + b)) -> tmps (split)
// ---------------------------------------------------------------------------
__global__ __launch_bounds__(256, 2) void node1_kernel(
    const uint2* __restrict__ xs, const uint2* __restrict__ aggs,
    const uint4* __restrict__ Wp, const float* __restrict__ Wb,
    const float* __restrict__ gam, const float* __restrict__ bet,
    uint2* __restrict__ tmps, int N) {
    extern __shared__ char smraw[];
    float* sBias = (float*)(smraw + SBIAS_OFF);
    float* sG    = (float*)(smraw + SG_OFF);
    float* sBv   = (float*)(smraw + SBV_OFF);

    const int tid = threadIdx.x;
    const int lane = tid & 31, warp = tid >> 5;
    const int wm = warp >> 2, wn = warp & 3;
    const int n0 = blockIdx.x * 64;
    const uint32_t sbase = (uint32_t)__cvta_generic_to_shared(smraw);
    const int arow = tid >> 2, apart = tid & 3;

    sBias[tid] = Wb[tid]; sG[tid] = gam[tid]; sBv[tid] = bet[tid];
    __syncthreads();

    int rowg = n0 + arow; if (rowg >= N) rowg = N - 1;

    float acc[2][8][4];
#pragma unroll
    for (int mt = 0; mt < 2; mt++)
#pragma unroll
        for (int nt = 0; nt < 8; nt++)
#pragma unroll
            for (int j = 0; j < 4; j++) acc[mt][nt][j] = 0.f;

    auto stageA = [&](int c, int buf) {
        const uint2* src = (c < 16 ? xs : aggs) + (size_t)rowg * 128 + (c & 15) * 8;
        cp16(sbase + SA_OFF + buf * 5120 + arow * 80 + apart * 16,
             (const char*)src + apart * 16);
    };
    gemm_pipeline(stageA, Wp, smraw, sbase, tid, wm, wn, lane, 32, acc);

    acc_to_sout(smraw, wm, wn, lane, acc, sBias);
    __syncthreads();
    float (*sOut)[260] = (float(*)[260])(smraw + SOUT_OFF);
#pragma unroll 1
    for (int i = 0; i < 8; i++) {
        int r = i * 8 + warp;
        float vv[8];
        *(float4*)&vv[0] = *(float4*)&sOut[r][lane * 4];
        *(float4*)&vv[4] = *(float4*)&sOut[r][128 + lane * 4];
        ln_silu_row(vv, lane, sG, sBv);
        int row = n0 + r;
        if (row < N) {
            uint2* op = tmps + (size_t)row * 128;
            op[lane * 2]          = split_pack(vv[0], vv[1]);
            op[lane * 2 + 1]      = split_pack(vv[2], vv[3]);
            op[64 + lane * 2]     = split_pack(vv[4], vv[5]);
            op[64 + lane * 2 + 1] = split_pack(vv[6], vv[7]);
        }
    }
}

// ---------------------------------------------------------------------------
// Node kernel 2: out = x + t@Wn2 + b2; also writes split xs for next layer
// ---------------------------------------------------------------------------
__global__ __launch_bounds__(256, 2) void node2_kernel(
    const uint2* __restrict__ tmps, const float* __restrict__ xres,
    const uint4* __restrict__ Wp, const float* __restrict__ Wb,
    float* __restrict__ out, uint2* __restrict__ xs_next, int N) {
    extern __shared__ char smraw[];
    float* sBias = (float*)(smraw + SBIAS_OFF);

    const int tid = threadIdx.x;
    const int lane = tid & 31, warp = tid >> 5;
    const int wm = warp >> 2, wn = warp & 3;
    const int n0 = blockIdx.x * 64;
    const uint32_t sbase = (uint32_t)__cvta_generic_to_shared(smraw);
    const int arow = tid >> 2, apart = tid & 3;

    sBias[tid] = Wb[tid];
    __syncthreads();

    int rowg = n0 + arow; if (rowg >= N) rowg = N - 1;

    float acc[2][8][4];
#pragma unroll
    for (int mt = 0; mt < 2; mt++)
#pragma unroll
        for (int nt = 0; nt < 8; nt++)
#pragma unroll
            for (int j = 0; j < 4; j++) acc[mt][nt][j] = 0.f;

    auto stageA = [&](int c, int buf) {
        const uint2* src = tmps + (size_t)rowg * 128 + c * 8;
        cp16(sbase + SA_OFF + buf * 5120 + arow * 80 + apart * 16,
             (const char*)src + apart * 16);
    };
    gemm_pipeline(stageA, Wp, smraw, sbase, tid, wm, wn, lane, 16, acc);

    acc_to_sout(smraw, wm, wn, lane, acc, sBias);
    __syncthreads();
    float (*sOut)[260] = (float(*)[260])(smraw + SOUT_OFF);
#pragma unroll 1
    for (int i = 0; i < 8; i++) {
        int r = i * 8 + warp;
        int row = n0 + r;
        if (row < N) {
            const float* xr = xres + (size_t)row * 256;
            float4 lo = *(float4*)&sOut[r][lane * 4];
            float4 hi = *(float4*)&sOut[r][128 + lane * 4];
            float4 xlo = *(const float4*)(xr + lane * 4);
            float4 xhi = *(const float4*)(xr + 128 + lane * 4);
            lo.x += xlo.x; lo.y += xlo.y; lo.z += xlo.z; lo.w += xlo.w;
            hi.x += xhi.x; hi.y += xhi.y; hi.z += xhi.z; hi.w += xhi.w;
            float* op = out + (size_t)row * 256;
            *(float4*)(op + lane * 4) = lo;
            *(float4*)(op + 128 + lane * 4) = hi;
            uint2* xp = xs_next + (size_t)row * 128;
            xp[lane * 2]          = split_pack(lo.x, lo.y);
            xp[lane * 2 + 1]      = split_pack(lo.z, lo.w);
            xp[64 + lane * 2]     = split_pack(hi.x, hi.y);
            xp[64 + lane * 2 + 1] = split_pack(hi.z, hi.w);
        }
    }
}

// ---------------------------------------------------------------------------
extern "C" void kernel_launch(void* const* d_in, const int* in_sizes, int n_in,
                              void* d_out, int out_size) {
    const float* x_in  = (const float*)d_in[0];
    const int*   eidx  = (const int*)d_in[1];
    const float* ea    = (const float*)d_in[2];
    const float* We_w  = (const float*)d_in[3];
    const float* We_b  = (const float*)d_in[4];
    const float* g1    = (const float*)d_in[5];
    const float* b1    = (const float*)d_in[6];
    const float* Wn1_w = (const float*)d_in[7];
    const float* Wn1_b = (const float*)d_in[8];
    const float* g2    = (const float*)d_in[9];
    const float* b2    = (const float*)d_in[10];
    const float* Wn2_w = (const float*)d_in[11];
    const float* Wn2_b = (const float*)d_in[12];

    const int N  = in_sizes[0] / 256;
    const int D  = in_sizes[1] / 2;
    const int NL = in_sizes[4] / 256;

    float *bufA, *bufB, *aggp, *y1p, *y2p;
    uint2 *xs, *aggs, *tmps;
    uint4 *wE, *wN1, *wN2;
    cudaGetSymbolAddress((void**)&bufA, g_bufA);
    cudaGetSymbolAddress((void**)&bufB, g_bufB);
    cudaGetSymbolAddress((void**)&aggp, g_agg);
    cudaGetSymbolAddress((void**)&y1p,  g_y1);
    cudaGetSymbolAddress((void**)&y2p,  g_y2);
    cudaGetSymbolAddress((void**)&xs,   g_xs);
    cudaGetSymbolAddress((void**)&aggs, g_aggs);
    cudaGetSymbolAddress((void**)&tmps, g_tmps);
    cudaGetSymbolAddress((void**)&wE,   g_We);
    cudaGetSymbolAddress((void**)&wN1,  g_Wn1);
    cudaGetSymbolAddress((void**)&wN2,  g_Wn2);

    cudaFuncSetAttribute(y12_kernel,   cudaFuncAttributeMaxDynamicSharedMemorySize, SMEM_BYTES);
    cudaFuncSetAttribute(node1_kernel, cudaFuncAttributeMaxDynamicSharedMemorySize, SMEM_BYTES);
    cudaFuncSetAttribute(node2_kernel, cudaFuncAttributeMaxDynamicSharedMemorySize, SMEM_BYTES);

    // one-time packs (deterministic, inside capture)
    {
        size_t t0 = (size_t)NL * 32 * 1024;
        pack_w_frag<<<(int)((t0 + 255) / 256), 256>>>(We_w, wE, 512, 516, 32, NL);
        pack_w_frag<<<(int)((t0 + 255) / 256), 256>>>(Wn1_w, wN1, 512, 512, 32, NL);
        size_t t2 = (size_t)NL * 16 * 1024;
        pack_w_frag<<<(int)((t2 + 255) / 256), 256>>>(Wn2_w, wN2, 256, 256, 16, NL);
        int nx = N * 128;
        convert_split<<<(nx + 255) / 256, 256>>>(x_in, xs, nx);
    }

    const int nblk_n = (N + 63) / 64;
    const int nblk_e = (D + 7) / 8;
    const int n4 = (N * 256) / 4;
    const int zblk = (n4 + 255) / 256;
    const int ncv = N * 128;
    const int cvblk = (ncv + 255) / 256;

    const float* xcur = x_in;
    for (int l = 0; l < NL; l++) {
        float* xnext = (l == NL - 1) ? (float*)d_out : ((l & 1) ? bufB : bufA);
        zero_kernel<<<zblk, 256>>>((float4*)aggp, n4);
        y12_kernel<<<dim3(nblk_n, 2), 256, SMEM_BYTES>>>(
            xs, wE + (size_t)l * 32 * 1024, y1p, y2p, N);
        edge_pass<<<nblk_e, 256>>>(
            y1p, y2p, eidx, ea,
            We_w + (size_t)l * 516 * 256 + (size_t)512 * 256,
            We_b + (size_t)l * 256, g1 + (size_t)l * 256, b1 + (size_t)l * 256,
            aggp, D);
        convert_split<<<cvblk, 256>>>(aggp, aggs, ncv);
        node1_kernel<<<nblk_n, 256, SMEM_BYTES>>>(
            xs, aggs, wN1 + (size_t)l * 32 * 1024,
            Wn1_b + (size_t)l * 256, g2 + (size_t)l * 256, b2 + (size_t)l * 256,
            tmps, N);
        node2_kernel<<<nblk_n, 256, SMEM_BYTES>>>(
            tmps, xcur, wN2 + (size_t)l * 16 * 1024,
            Wn2_b + (size_t)l * 256, xnext, xs, N);
        xcur = xnext;
    }
}